// round 15
// baseline (speedup 1.0000x reference)
#include <cuda_runtime.h>
#include <cuda_bf16.h>
#include <cuda_fp16.h>
#include <cstdint>

#define HW    192
#define NPIX  36864
#define CH    64
#define WS    48
#define NTOK  2304
#define NWIN  16
#define TOTTOK 36864

// ---------------- scratch (device globals; no allocations) ----------------
__device__ __align__(16) __nv_bfloat16 g_Kb[NWIN*NTOK*CH];   // [win][n][d]
__device__ __align__(16) __nv_bfloat16 g_Vb[NWIN*NTOK*CH];   // [win][n][d]
__device__ __align__(16) float g_U [TOTTOK];                 // 0 = active, -150 = masked
__device__ __align__(16) __half g_refh[NPIX*CH];             // refined, fp16 NHWC [pix][c]
__device__ __align__(16) __nv_bfloat16 g_Mb[CH*CH];          // fused W1*Wout, bf16 [c][d]
__device__ __align__(16) float g_b2[CH];
__device__ __align__(16) __half g_W3h[9*CH*CH];              // conv w fp16 [tap][oc][ch]

// ---------------- PTX helpers ----------------------------------------------
__device__ __forceinline__ uint32_t smem_to_u32(const void* p) {
    uint32_t a;
    asm("{ .reg .u64 t; cvta.to.shared.u64 t, %1; cvt.u32.u64 %0, t; }" : "=r"(a) : "l"(p));
    return a;
}

#define CP16(dst, src) \
    asm volatile("cp.async.cg.shared.global [%0], [%1], 16;" :: "r"(dst), "l"(src) : "memory")
#define CP16Z(dst, src, n) \
    asm volatile("cp.async.cg.shared.global [%0], [%1], 16, %2;" :: "r"(dst), "l"(src), "r"(n) : "memory")
#define CP4(dst, src) \
    asm volatile("cp.async.ca.shared.global [%0], [%1], 4;" :: "r"(dst), "l"(src) : "memory")
#define CP_COMMIT() asm volatile("cp.async.commit_group;" ::: "memory")
#define CP_WAIT0()  asm volatile("cp.async.wait_group 0;" ::: "memory")
#define CP_WAIT1()  asm volatile("cp.async.wait_group 1;" ::: "memory")

#define LDSM_X4(r0,r1,r2,r3,addr) \
    asm volatile("ldmatrix.sync.aligned.m8n8.x4.shared.b16 {%0,%1,%2,%3}, [%4];" \
        : "=r"(r0), "=r"(r1), "=r"(r2), "=r"(r3) : "r"(addr))
#define LDSM_X4T(r0,r1,r2,r3,addr) \
    asm volatile("ldmatrix.sync.aligned.m8n8.x4.trans.shared.b16 {%0,%1,%2,%3}, [%4];" \
        : "=r"(r0), "=r"(r1), "=r"(r2), "=r"(r3) : "r"(addr))

#define MMA_BF16(c, a0,a1,a2,a3, b0,b1) \
    asm volatile("mma.sync.aligned.m16n8k16.row.col.f32.bf16.bf16.f32 " \
        "{%0,%1,%2,%3}, {%4,%5,%6,%7}, {%8,%9}, {%0,%1,%2,%3};" \
        : "+f"((c)[0]), "+f"((c)[1]), "+f"((c)[2]), "+f"((c)[3]) \
        : "r"(a0), "r"(a1), "r"(a2), "r"(a3), "r"(b0), "r"(b1))

#define MMA_F16(c, a0,a1,a2,a3, b0,b1) \
    asm volatile("mma.sync.aligned.m16n8k16.row.col.f32.f16.f16.f32 " \
        "{%0,%1,%2,%3}, {%4,%5,%6,%7}, {%8,%9}, {%0,%1,%2,%3};" \
        : "+f"((c)[0]), "+f"((c)[1]), "+f"((c)[2]), "+f"((c)[3]) \
        : "r"(a0), "r"(a1), "r"(a2), "r"(a3), "r"(b0), "r"(b1))

#define CVT_BF16X2(result, lo, hi) \
    asm("cvt.rn.satfinite.bf16x2.f32 %0, %1, %2;" : "=r"(result) : "f"(hi), "f"(lo))
#define EX2F(r, x) asm("ex2.approx.ftz.f32 %0, %1;" : "=f"(r) : "f"(x))

__device__ __forceinline__ uint32_t pack_h2(float lo, float hi) {
    __half2 h = __floats2half2_rn(lo, hi);
    return *(uint32_t*)&h;
}

// ---------------- kernel 1: K/V projections + fused prep -------------------
// blocks [0,288): K/V projection; blocks [288,290): prep (g_Mb, g_b2, g_W3h).
#define XS_STRIDE 132
#define KV_WF   (64*XS_STRIDE)                    // fp32 Wk/Wv staging [128][64]
#define KV_WSB  (KV_WF + 128*64)                  // bf16x2 Wsb [128][36]
#define KV_BS   (KV_WSB + 128*36)                 // bias [128]
#define KV_SMEM ((KV_BS + 128)*4)
__global__ void __launch_bounds__(256) kv_kernel(
    const float* __restrict__ rf, const float* __restrict__ unc,
    const float* __restrict__ ipb, const float* __restrict__ ipw,
    const float* __restrict__ w1, const float* __restrict__ b1,
    const float* __restrict__ wo, const float* __restrict__ bo,
    const float* __restrict__ w3)
{
    int tid = threadIdx.x;

    if (blockIdx.x >= 288) {                      // ---- fused prep ----
        int idx0 = (blockIdx.x - 288)*256 + tid;  // 0..511
        int i = idx0 >> 3;                        // in-channel
        int jb = (idx0 & 7)*8;
#pragma unroll
        for (int k = 0; k < 8; k++) {
            int j = jb + k;
            float acc = 0.f;
            for (int kk = 0; kk < 64; kk++) acc += w1[i*64+kk] * wo[kk*64+j];
            g_Mb[i*64+j] = __float2bfloat16_rn(acc);
#pragma unroll
            for (int tap = 0; tap < 9; tap++)
                g_W3h[(tap*64 + j)*64 + i] = __float2half_rn(w3[(j*64 + i)*9 + tap]);
        }
        if ((idx0 & 7) == 0) {
            float a = b1[i];
            for (int kk = 0; kk < 64; kk++) a += w1[i*64+kk] * bo[kk];
            g_b2[i] = a;
        }
        return;
    }

    extern __shared__ float qsm[];
    float* Rs = qsm;                              // [64][132]
    float* Wf = qsm + KV_WF;                      // [128][64] fp32
    uint32_t* Wsb = (uint32_t*)(qsm + KV_WSB);    // [128][36] bf16x2
    float* bs = qsm + KV_BS;                      // [128]
    uint32_t smem = smem_to_u32(qsm);

    int wid = tid >> 5, l = tid & 31;
    int t0  = blockIdx.x * 128;
    int win = blockIdx.x / 18;
    int nbase = (blockIdx.x % 18) * 128;
    int pixbase = (win >> 2)*WS*HW + (win & 3)*WS;

#pragma unroll
    for (int it = 0; it < 8; it++) {
        int gidx = it*256 + tid;
        int c = gidx >> 5, g = gidx & 31;
        int n = nbase + g*4;
        int pix = pixbase + (n/WS)*HW + (n%WS);
        CP16(smem + (c*XS_STRIDE + g*4)*4, rf + c*NPIX + pix);
    }
#pragma unroll
    for (int i = tid; i < 2048; i += 256) {       // Wk/Wv fp32 rows 64..191
        int o = i >> 4, q = i & 15;
        CP16(smem + (KV_WF + o*64 + q*4)*4, ipw + (64 + o)*64 + q*4);
    }
    if (tid < 128) CP4(smem + (KV_BS + tid)*4, ipb + 64 + tid);
    CP_COMMIT();

    if (tid < 128) {
        int n = nbase + tid;
        int pix = pixbase + (n/WS)*HW + (n%WS);
        g_U[t0 + tid] = (unc[pix] > 0.01f) ? 0.f : -150.f;
    }

    CP_WAIT0();
    __syncthreads();

    // pack fp32 W -> bf16x2 Wsb layout
#pragma unroll
    for (int i = tid; i < 4096; i += 256) {
        int o = i >> 5, u = i & 31;
        CVT_BF16X2(Wsb[o*36 + u], Wf[o*64 + 2*u], Wf[o*64 + 2*u + 1]);
    }
    __syncthreads();

    int r = wid*16 + (l >> 2);
    uint32_t ar[4][4];
#pragma unroll
    for (int kk = 0; kk < 4; kk++) {
        int k0 = kk*16 + 2*(l & 3);
#pragma unroll
        for (int half = 0; half < 2; half++) {
            int k = k0 + half*8;
            CVT_BF16X2(ar[kk][2*half],   Rs[k*XS_STRIDE + r],     Rs[(k+1)*XS_STRIDE + r]);
            CVT_BF16X2(ar[kk][2*half+1], Rs[k*XS_STRIDE + r + 8], Rs[(k+1)*XS_STRIDE + r + 8]);
        }
    }

#pragma unroll
    for (int seg = 0; seg < 2; seg++) {
        float acc[8][4];
#pragma unroll
        for (int nb = 0; nb < 8; nb++)
#pragma unroll
            for (int c = 0; c < 4; c++) acc[nb][c] = 0.f;

#pragma unroll
        for (int nb = 0; nb < 8; nb++) {
            int o = seg*64 + nb*8 + (l >> 2);
#pragma unroll
            for (int kk = 0; kk < 4; kk++) {
                uint32_t b0 = Wsb[o*36 + kk*8 + (l & 3)];
                uint32_t b1 = Wsb[o*36 + kk*8 + (l & 3) + 4];
                MMA_BF16(acc[nb], ar[kk][0], ar[kk][1], ar[kk][2], ar[kk][3], b0, b1);
            }
        }

        __nv_bfloat16* dst = (seg == 0) ? g_Kb : g_Vb;
#pragma unroll
        for (int nb = 0; nb < 8; nb++) {
            int col = nb*8 + 2*(l & 3);
            float bv0 = bs[seg*64 + col], bv1 = bs[seg*64 + col + 1];
            uint32_t lo, hi;
            CVT_BF16X2(lo, acc[nb][0] + bv0, acc[nb][1] + bv1);
            CVT_BF16X2(hi, acc[nb][2] + bv0, acc[nb][3] + bv1);
            *(uint32_t*)(dst + (size_t)(t0 + r)*64 + col)     = lo;
            *(uint32_t*)(dst + (size_t)(t0 + r + 8)*64 + col) = hi;
        }
    }
}

// ---------------- kernel 2: attn with fused Q-projection + refine ---------
#define QOFF   0
#define KOFF   16384
#define VOFF   49152
#define UCOFF  81920
#define ATTN_SMEM (81920 + 1024)

__device__ __forceinline__ void issue_tile(uint32_t smem, int win, int ct, int buf, int tid)
{
    int c0 = ct * 128;
    const char* Kg = (const char*)g_Kb + ((size_t)(win*NTOK + c0))*128;
    const char* Vg = (const char*)g_Vb + ((size_t)(win*NTOK + c0))*128;
    uint32_t kb = smem + KOFF + buf*16384;
    uint32_t vb = smem + VOFF + buf*16384;
#pragma unroll
    for (int i = 0; i < 4; i++) {
        int li = i*256 + tid, r = li >> 3, q = li & 7;
        uint32_t off = r*128 + ((q*16) ^ ((r & 7) << 4));
        CP16(kb + off, Kg + r*128 + q*16);
        CP16(vb + off, Vg + r*128 + q*16);
    }
    if (tid < 128)
        CP4(smem + UCOFF + buf*512 + tid*4, (const char*)(g_U + win*NTOK + c0 + tid));
}

__global__ void __launch_bounds__(256, 2) attn_kernel(const float* __restrict__ x,
                                                      const float* __restrict__ ipb,
                                                      const float* __restrict__ ipw)
{
    extern __shared__ char smc[];
    uint32_t smem = smem_to_u32(smc);
    int tid = threadIdx.x, wid = tid >> 5, l = tid & 31;
    int win = blockIdx.y, r0 = blockIdx.x * 128;
    int pixbase = (win >> 2)*WS*HW + (win & 3)*WS;
    const float LC = 0.18033688011112042f;   // 0.125 * log2(e)

    // ---- prologue: x tile (fp32) into K region; Wq fp32 into 2nd V buffer
#pragma unroll
    for (int it = 0; it < 8; it++) {
        int gidx = it*256 + tid;
        int c = gidx >> 5, g = gidx & 31;
        int n = r0 + g*4;
        int pix = pixbase + (n/WS)*HW + (n%WS);
        CP16(smem + KOFF + (c*XS_STRIDE + g*4)*4, x + c*NPIX + pix);
    }
#pragma unroll
    for (int i = tid; i < 1024; i += 256) {       // Wq rows 0..63 fp32, 16 KB
        int o = i >> 4, q = i & 15;
        CP16(smem + VOFF + 16384 + (o*64 + q*4)*4, ipw + o*64 + q*4);
    }
    if (tid < 64) CP4(smem + QOFF + 9216 + tid*4, ipb + tid);
    CP_COMMIT();

    int row_a = wid*16 + (l >> 2);
    bool urow0 = g_U[win*NTOK + r0 + row_a]     > -1.f;
    bool urow1 = g_U[win*NTOK + r0 + row_a + 8] > -1.f;
    float LC0 = urow0 ? LC : 0.f;
    float LC1 = urow1 ? LC : 0.f;
    float M0 = urow0 ? 1.f : 0.f;
    float M1 = urow1 ? 1.f : 0.f;

    CP_WAIT0();
    __syncthreads();

    // build x A-fragments from fp32 smem
    uint32_t axf[4][4];
    {
        const float* Xs = (const float*)(smc + KOFF);
        int r = row_a;
#pragma unroll
        for (int kk = 0; kk < 4; kk++) {
            int k0 = kk*16 + 2*(l & 3);
#pragma unroll
            for (int half = 0; half < 2; half++) {
                int k = k0 + half*8;
                CVT_BF16X2(axf[kk][2*half],   Xs[k*XS_STRIDE + r],     Xs[(k+1)*XS_STRIDE + r]);
                CVT_BF16X2(axf[kk][2*half+1], Xs[k*XS_STRIDE + r + 8], Xs[(k+1)*XS_STRIDE + r + 8]);
            }
        }
    }
    // pack Wq fp32 -> bf16x2 Wsb at QOFF
    {
        const float* Wf = (const float*)(smc + VOFF + 16384);
        uint32_t* Wsb = (uint32_t*)(smc + QOFF);
#pragma unroll
        for (int i = tid; i < 2048; i += 256) {
            int o = i >> 5, u = i & 31;
            CVT_BF16X2(Wsb[o*36 + u], Wf[o*64 + 2*u], Wf[o*64 + 2*u + 1]);
        }
    }
    __syncthreads();                              // x + Wq reads done

    issue_tile(smem, win, 0, 0, tid);
    CP_COMMIT();
    issue_tile(smem, win, 1, 1, tid);
    CP_COMMIT();

    // Q = x*Wq^T (+bq), accumulators repacked directly as S-GEMM A-fragments
    uint32_t qa[4][4];
    {
        const uint32_t* Wsb = (const uint32_t*)(smc + QOFF);
        const float* bq = (const float*)(smc + QOFF + 9216);
        float accQ[8][4];
#pragma unroll
        for (int nb = 0; nb < 8; nb++)
#pragma unroll
            for (int c = 0; c < 4; c++) accQ[nb][c] = 0.f;
#pragma unroll
        for (int nb = 0; nb < 8; nb++) {
            int o = nb*8 + (l >> 2);
#pragma unroll
            for (int kk = 0; kk < 4; kk++) {
                uint32_t b0 = Wsb[o*36 + kk*8 + (l & 3)];
                uint32_t b1 = Wsb[o*36 + kk*8 + (l & 3) + 4];
                MMA_BF16(accQ[nb], axf[kk][0], axf[kk][1], axf[kk][2], axf[kk][3], b0, b1);
            }
        }
#pragma unroll
        for (int kk = 0; kk < 4; kk++) {
            int c0 = kk*16 + 2*(l & 3);
            float b0v = bq[c0],     b1v = bq[c0 + 1];
            float b8v = bq[c0 + 8], b9v = bq[c0 + 9];
            CVT_BF16X2(qa[kk][0], accQ[2*kk][0] + b0v,   accQ[2*kk][1] + b1v);
            CVT_BF16X2(qa[kk][1], accQ[2*kk][2] + b0v,   accQ[2*kk][3] + b1v);
            CVT_BF16X2(qa[kk][2], accQ[2*kk+1][0] + b8v, accQ[2*kk+1][1] + b9v);
            CVT_BF16X2(qa[kk][3], accQ[2*kk+1][2] + b8v, accQ[2*kk+1][3] + b9v);
        }
    }

    float o[8][4];
#pragma unroll
    for (int j = 0; j < 8; j++)
#pragma unroll
        for (int c = 0; c < 4; c++) o[j][c] = 0.f;
    float rsum0 = 0.f, rsum1 = 0.f;

    int m = l >> 3;
    uint32_t xr = (uint32_t)(l & 7) << 4;
    int nrow_b = (m >> 1)*8 + (l & 7);
    int krow_b = (m & 1)*8 + (l & 7);
    const float* ucsm = (const float*)(smc + UCOFF);

    CP_WAIT1();
    __syncthreads();

#pragma unroll 1
    for (int ct = 0; ct < 18; ct++) {
        uint32_t kb = smem + KOFF + (ct & 1)*16384;
        uint32_t vb = smem + VOFF + (ct & 1)*16384;

#pragma unroll
        for (int h = 0; h < 2; h++) {
            float s[8][4];
#pragma unroll
            for (int j = 0; j < 8; j++)
#pragma unroll
                for (int c = 0; c < 4; c++) s[j][c] = 0.f;

#pragma unroll
            for (int kk = 0; kk < 4; kk++) {
                uint32_t cb = ((uint32_t)(kk*32 + (m & 1)*16)) ^ xr;
#pragma unroll
                for (int jb = 0; jb < 4; jb++) {
                    uint32_t addr = kb + (16*(4*h + jb) + nrow_b)*128 + cb;
                    uint32_t b0, b1, b2, b3;
                    LDSM_X4(b0, b1, b2, b3, addr);
                    MMA_BF16(s[2*jb],   qa[kk][0], qa[kk][1], qa[kk][2], qa[kk][3], b0, b1);
                    MMA_BF16(s[2*jb+1], qa[kk][0], qa[kk][1], qa[kk][2], qa[kk][3], b2, b3);
                }
            }

            const float* ucb = ucsm + (ct & 1)*128 + h*64 + 2*(l & 3);
            uint32_t pc01[8], pc23[8];
#pragma unroll
            for (int j = 0; j < 8; j++) {
                float2 cm = *(const float2*)(ucb + 8*j);
                float p0, p1, p2, p3;
                EX2F(p0, fmaf(s[j][0], LC0, cm.x*M0));
                EX2F(p1, fmaf(s[j][1], LC0, cm.y*M0));
                EX2F(p2, fmaf(s[j][2], LC1, cm.x*M1));
                EX2F(p3, fmaf(s[j][3], LC1, cm.y*M1));
                rsum0 += p0 + p1;
                rsum1 += p2 + p3;
                CVT_BF16X2(pc01[j], p0, p1);
                CVT_BF16X2(pc23[j], p2, p3);
            }

#pragma unroll
            for (int kc = 0; kc < 4; kc++) {
                uint32_t ra = vb + (16*(4*h + kc) + krow_b)*128;
#pragma unroll
                for (int jb = 0; jb < 4; jb++) {
                    uint32_t addr = ra + (((uint32_t)(jb*32 + (m >> 1)*16)) ^ xr);
                    uint32_t v0, v1, v2, v3;
                    LDSM_X4T(v0, v1, v2, v3, addr);
                    MMA_BF16(o[2*jb],   pc01[2*kc], pc23[2*kc], pc01[2*kc+1], pc23[2*kc+1], v0, v1);
                    MMA_BF16(o[2*jb+1], pc01[2*kc], pc23[2*kc], pc01[2*kc+1], pc23[2*kc+1], v2, v3);
                }
            }
        }

        __syncthreads();
        if (ct + 2 < 18) { issue_tile(smem, win, ct + 2, ct & 1, tid); CP_COMMIT(); }
        if (ct + 1 < 18) {
            if (ct + 2 < 18) { CP_WAIT1(); } else { CP_WAIT0(); }
            __syncthreads();
        }
    }

    rsum0 += __shfl_xor_sync(0xffffffffu, rsum0, 1);
    rsum0 += __shfl_xor_sync(0xffffffffu, rsum0, 2);
    rsum1 += __shfl_xor_sync(0xffffffffu, rsum1, 1);
    rsum1 += __shfl_xor_sync(0xffffffffu, rsum1, 2);
    float inv0 = 1.f / rsum0, inv1 = 1.f / rsum1;

    // fused refine: refined = x + (O/rsum)*M^T + b2, written fp16 NHWC
    __syncthreads();
    {
        const char* Mg = (const char*)g_Mb;
#pragma unroll
        for (int i = 0; i < 2; i++) {
            int li = i*256 + tid, r = li >> 3, q = li & 7;
            CP16(smem + QOFF + r*128 + ((q*16) ^ ((r & 7) << 4)), Mg + r*128 + q*16);
        }
        CP_COMMIT(); CP_WAIT0();
    }
    __syncthreads();

    uint32_t af[4][4];
#pragma unroll
    for (int kk = 0; kk < 4; kk++) {
        CVT_BF16X2(af[kk][0], o[2*kk][0]*inv0,   o[2*kk][1]*inv0);
        CVT_BF16X2(af[kk][1], o[2*kk][2]*inv1,   o[2*kk][3]*inv1);
        CVT_BF16X2(af[kk][2], o[2*kk+1][0]*inv0, o[2*kk+1][1]*inv0);
        CVT_BF16X2(af[kk][3], o[2*kk+1][2]*inv1, o[2*kk+1][3]*inv1);
    }

    float dd[8][4];
#pragma unroll
    for (int j = 0; j < 8; j++)
#pragma unroll
        for (int c = 0; c < 4; c++) dd[j][c] = 0.f;

#pragma unroll
    for (int kk = 0; kk < 4; kk++) {
        uint32_t cb = ((uint32_t)(kk*32 + (m & 1)*16)) ^ xr;
#pragma unroll
        for (int jb = 0; jb < 4; jb++) {
            uint32_t addr = smem + QOFF + (16*jb + nrow_b)*128 + cb;
            uint32_t b0, b1, b2, b3;
            LDSM_X4(b0, b1, b2, b3, addr);
            MMA_BF16(dd[2*jb],   af[kk][0], af[kk][1], af[kk][2], af[kk][3], b0, b1);
            MMA_BF16(dd[2*jb+1], af[kk][0], af[kk][1], af[kk][2], af[kk][3], b2, b3);
        }
    }

    int n0 = r0 + row_a;
    int n1 = n0 + 8;
    int px0 = pixbase + (n0/WS)*HW + n0%WS;
    int px1 = pixbase + (n1/WS)*HW + n1%WS;
#pragma unroll
    for (int jb = 0; jb < 4; jb++) {
#pragma unroll
        for (int hh = 0; hh < 2; hh++) {
            int c = 16*jb + 8*hh + 2*(l & 3);
            int j = 2*jb + hh;
            float2 b2v = *(const float2*)(g_b2 + c);
            *(uint32_t*)(g_refh + (size_t)px0*64 + c) =
                pack_h2(x[(size_t)c*NPIX + px0]     + dd[j][0] + b2v.x,
                        x[(size_t)(c+1)*NPIX + px0] + dd[j][1] + b2v.y);
            *(uint32_t*)(g_refh + (size_t)px1*64 + c) =
                pack_h2(x[(size_t)c*NPIX + px1]     + dd[j][2] + b2v.x,
                        x[(size_t)(c+1)*NPIX + px1] + dd[j][3] + b2v.y);
        }
    }
}

// ---------------- kernel 3: conv3x3 fp16 MMA via ldmatrix (R13 proven) ----
#define CONVW_OFF 0
#define CONVI_OFF 73728
#define CONV_SMEM (73728 + 43520 + 256)

__global__ void __launch_bounds__(256) conv_kernel(
    const float* __restrict__ b3, const float* __restrict__ w4,
    const float* __restrict__ b4v, float* __restrict__ out)
{
    extern __shared__ char csm[];
    uint32_t smem = smem_to_u32(csm);

    int tid = threadIdx.x, wid = tid >> 5, l = tid & 31;
    int cx0 = blockIdx.x*32, y0 = blockIdx.y*8;

    for (int i = tid; i < 4608; i += 256) {
        int row = i >> 3, q = i & 7;
        CP16(smem + CONVW_OFF + row*128 + ((q*16) ^ ((row & 7) << 4)),
             g_W3h + row*64 + q*8);
    }
    for (int i = tid; i < 2720; i += 256) {
        int p = i >> 3, q = i & 7;
        int ry = p / 34, rcx = p - ry*34;
        int gy = y0 - 1 + ry, gx = cx0 - 1 + rcx;
        bool ok = ((unsigned)gy < HW) && ((unsigned)gx < HW);
        const __half* src = g_refh + ((size_t)(ok ? (gy*HW + gx) : 0))*64 + q*8;
        CP16Z(smem + CONVI_OFF + p*128 + ((q*16) ^ ((p & 7) << 4)),
              src, ok ? 16u : 0u);
    }
    CP_COMMIT();
    CP_WAIT0();
    __syncthreads();

    float acc[2][8][4];
#pragma unroll
    for (int mb = 0; mb < 2; mb++)
#pragma unroll
        for (int nb = 0; nb < 8; nb++)
#pragma unroll
            for (int c = 0; c < 4; c++) acc[mb][nb][c] = 0.f;

    int m = l >> 3;
    int wr = wid;

#pragma unroll 1
    for (int tap = 0; tap < 9; tap++) {
        int dyv = tap / 3, dxv = tap % 3;
        int arow_base = (wr + dyv)*34 + dxv + (m & 1)*8 + (l & 7);
#pragma unroll
        for (int kk = 0; kk < 4; kk++) {
            uint32_t bf[8][2];
#pragma unroll
            for (int jb = 0; jb < 4; jb++) {
                uint32_t addr = smem + CONVW_OFF
                    + (tap*64 + 16*jb + (m >> 1)*8 + (l & 7))*128
                    + (((uint32_t)(kk*32 + (m & 1)*16)) ^ ((uint32_t)(l & 7) << 4));
                LDSM_X4(bf[2*jb][0], bf[2*jb][1], bf[2*jb+1][0], bf[2*jb+1][1], addr);
            }
#pragma unroll
            for (int mb = 0; mb < 2; mb++) {
                int arow = arow_base + 16*mb;
                uint32_t addr = smem + CONVI_OFF + arow*128 +
                    (((uint32_t)(kk*32 + (m >> 1)*16)) ^ (((uint32_t)(arow & 7)) << 4));
                uint32_t a0, a1, a2, a3;
                LDSM_X4(a0, a1, a2, a3, addr);
#pragma unroll
                for (int nb = 0; nb < 8; nb++)
                    MMA_F16(acc[mb][nb], a0, a1, a2, a3, bf[nb][0], bf[nb][1]);
            }
        }
    }

    int y = y0 + wr;
    float b4 = b4v[0];
    float s[2][2] = {{0.f, 0.f}, {0.f, 0.f}};
#pragma unroll
    for (int mb = 0; mb < 2; mb++) {
        int x1 = cx0 + 16*mb + (l >> 2);
        int x2 = x1 + 8;
#pragma unroll
        for (int nb = 0; nb < 8; nb++) {
            int oc = 8*nb + 2*(l & 3);
            float bv0 = __ldg(b3 + oc), bv1 = __ldg(b3 + oc + 1);
            float w40 = __ldg(w4 + oc), w41 = __ldg(w4 + oc + 1);
            float r00 = fmaxf(acc[mb][nb][0] + bv0, 0.f);
            float r01 = fmaxf(acc[mb][nb][1] + bv1, 0.f);
            float r10 = fmaxf(acc[mb][nb][2] + bv0, 0.f);
            float r11 = fmaxf(acc[mb][nb][3] + bv1, 0.f);
            out[(size_t)oc*NPIX     + y*HW + x1] = r00;
            out[(size_t)(oc+1)*NPIX + y*HW + x1] = r01;
            out[(size_t)oc*NPIX     + y*HW + x2] = r10;
            out[(size_t)(oc+1)*NPIX + y*HW + x2] = r11;
            s[mb][0] += r00*w40 + r01*w41;
            s[mb][1] += r10*w40 + r11*w41;
        }
    }
#pragma unroll
    for (int mb = 0; mb < 2; mb++) {
#pragma unroll
        for (int h = 0; h < 2; h++) {
            s[mb][h] += __shfl_xor_sync(0xffffffffu, s[mb][h], 1);
            s[mb][h] += __shfl_xor_sync(0xffffffffu, s[mb][h], 2);
        }
    }
    if ((l & 3) == 0) {
#pragma unroll
        for (int mb = 0; mb < 2; mb++) {
            int x1 = cx0 + 16*mb + (l >> 2);
            out[(size_t)64*NPIX + y*HW + x1]     = s[mb][0] + b4;
            out[(size_t)64*NPIX + y*HW + x1 + 8] = s[mb][1] + b4;
        }
    }
    {
        int yy = y0 + (tid >> 5), xx = cx0 + (tid & 31);
        int ry = yy % WS, rx = xx % WS;
        float pm = ((ry == 0) | (ry == WS-1) | (rx == 0) | (rx == WS-1)) ? 0.6f : 1.0f;
        out[(size_t)65*NPIX + yy*HW + xx] = pm;
    }
}

// ---------------- launch ---------------------------------------------------
extern "C" void kernel_launch(void* const* d_in, const int* in_sizes, int n_in,
                              void* d_out, int out_size)
{
    const float* x    = (const float*)d_in[0];
    const float* rf   = (const float*)d_in[1];
    const float* unc  = (const float*)d_in[2];
    const float* ipw  = (const float*)d_in[3];
    const float* ipb  = (const float*)d_in[4];
    const float* wout = (const float*)d_in[5];
    const float* bout = (const float*)d_in[6];
    const float* w1   = (const float*)d_in[7];
    const float* b1   = (const float*)d_in[8];
    const float* w3   = (const float*)d_in[9];
    const float* b3   = (const float*)d_in[10];
    const float* w4   = (const float*)d_in[11];
    const float* b4   = (const float*)d_in[12];
    float* out = (float*)d_out;

    static bool attr_set = false;
    if (!attr_set) {
        cudaFuncSetAttribute(attn_kernel, cudaFuncAttributeMaxDynamicSharedMemorySize, ATTN_SMEM);
        cudaFuncSetAttribute(conv_kernel, cudaFuncAttributeMaxDynamicSharedMemorySize, CONV_SMEM);
        cudaFuncSetAttribute(kv_kernel, cudaFuncAttributeMaxDynamicSharedMemorySize, KV_SMEM);
        attr_set = true;
    }

    kv_kernel<<<290, 256, KV_SMEM>>>(rf, unc, ipb, ipw, w1, b1, wout, bout, w3);
    dim3 ag(18, 16);
    attn_kernel<<<ag, 256, ATTN_SMEM>>>(x, ipb, ipw);
    dim3 cg(6, 24);
    conv_kernel<<<cg, 256, CONV_SMEM>>>(b3, w4, b4, out);
}

// round 16
// speedup vs baseline: 1.0660x; 1.0660x over previous
#include <cuda_runtime.h>
#include <cuda_bf16.h>
#include <cuda_fp16.h>
#include <cstdint>

#define HW    192
#define NPIX  36864
#define CH    64
#define WS    48
#define NTOK  2304
#define NWIN  16
#define TOTTOK 36864

// ---------------- scratch (device globals; no allocations) ----------------
__device__ __align__(16) __nv_bfloat16 g_Kb[NWIN*NTOK*CH];   // [win][n][d]
__device__ __align__(16) __nv_bfloat16 g_Vb[NWIN*NTOK*CH];   // [win][n][d]
__device__ __align__(16) float g_U [TOTTOK];                 // 0 = active, -150 = masked
__device__ __align__(16) __half g_refh[NPIX*CH];             // refined, fp16 NHWC [pix][c]
__device__ __align__(16) __nv_bfloat16 g_Mb[CH*CH];          // fused W1*Wout, bf16 [c][d]
__device__ __align__(16) float g_b2[CH];
__device__ __align__(16) __half g_W3h[9*CH*CH];              // conv w fp16 [tap][oc][ch]

// ---------------- PTX helpers ----------------------------------------------
__device__ __forceinline__ uint32_t smem_to_u32(const void* p) {
    uint32_t a;
    asm("{ .reg .u64 t; cvta.to.shared.u64 t, %1; cvt.u32.u64 %0, t; }" : "=r"(a) : "l"(p));
    return a;
}

#define CP16(dst, src) \
    asm volatile("cp.async.cg.shared.global [%0], [%1], 16;" :: "r"(dst), "l"(src) : "memory")
#define CP16Z(dst, src, n) \
    asm volatile("cp.async.cg.shared.global [%0], [%1], 16, %2;" :: "r"(dst), "l"(src), "r"(n) : "memory")
#define CP4(dst, src) \
    asm volatile("cp.async.ca.shared.global [%0], [%1], 4;" :: "r"(dst), "l"(src) : "memory")
#define CP_COMMIT() asm volatile("cp.async.commit_group;" ::: "memory")
#define CP_WAIT0()  asm volatile("cp.async.wait_group 0;" ::: "memory")
#define CP_WAIT1()  asm volatile("cp.async.wait_group 1;" ::: "memory")

#define LDSM_X4(r0,r1,r2,r3,addr) \
    asm volatile("ldmatrix.sync.aligned.m8n8.x4.shared.b16 {%0,%1,%2,%3}, [%4];" \
        : "=r"(r0), "=r"(r1), "=r"(r2), "=r"(r3) : "r"(addr))
#define LDSM_X4T(r0,r1,r2,r3,addr) \
    asm volatile("ldmatrix.sync.aligned.m8n8.x4.trans.shared.b16 {%0,%1,%2,%3}, [%4];" \
        : "=r"(r0), "=r"(r1), "=r"(r2), "=r"(r3) : "r"(addr))

#define MMA_BF16(c, a0,a1,a2,a3, b0,b1) \
    asm volatile("mma.sync.aligned.m16n8k16.row.col.f32.bf16.bf16.f32 " \
        "{%0,%1,%2,%3}, {%4,%5,%6,%7}, {%8,%9}, {%0,%1,%2,%3};" \
        : "+f"((c)[0]), "+f"((c)[1]), "+f"((c)[2]), "+f"((c)[3]) \
        : "r"(a0), "r"(a1), "r"(a2), "r"(a3), "r"(b0), "r"(b1))

#define MMA_F16(c, a0,a1,a2,a3, b0,b1) \
    asm volatile("mma.sync.aligned.m16n8k16.row.col.f32.f16.f16.f32 " \
        "{%0,%1,%2,%3}, {%4,%5,%6,%7}, {%8,%9}, {%0,%1,%2,%3};" \
        : "+f"((c)[0]), "+f"((c)[1]), "+f"((c)[2]), "+f"((c)[3]) \
        : "r"(a0), "r"(a1), "r"(a2), "r"(a3), "r"(b0), "r"(b1))

#define CVT_BF16X2(result, lo, hi) \
    asm("cvt.rn.satfinite.bf16x2.f32 %0, %1, %2;" : "=r"(result) : "f"(hi), "f"(lo))
#define EX2F(r, x) asm("ex2.approx.ftz.f32 %0, %1;" : "=f"(r) : "f"(x))

__device__ __forceinline__ uint32_t pack_h2(float lo, float hi) {
    __half2 h = __floats2half2_rn(lo, hi);
    return *(uint32_t*)&h;
}

// ---------------- kernel 0: prep (g_Mb, g_b2, g_W3h) -----------------------
__global__ void prep_kernel(const float* __restrict__ w1, const float* __restrict__ b1,
                            const float* __restrict__ wo, const float* __restrict__ bo,
                            const float* __restrict__ w3)
{
    int i = blockIdx.x, j = threadIdx.x;     // i = in-channel c, j = out-channel o
    float acc = 0.f;
    for (int k = 0; k < 64; k++) acc += w1[i*64+k] * wo[k*64+j];
    g_Mb[i*64+j] = __float2bfloat16_rn(acc);
    if (j == 0) {
        float a = b1[i];
        for (int k = 0; k < 64; k++) a += w1[i*64+k] * bo[k];
        g_b2[i] = a;
    }
#pragma unroll
    for (int tap = 0; tap < 9; tap++)
        g_W3h[(tap*64 + j)*64 + i] = __float2half_rn(w3[(j*64 + i)*9 + tap]);
}

// ---------------- kernel 1: K/V projections via bf16 MMA -------------------
// Slim smem (51 KB): rf tile + bf16x2 Wsb only -> 2 CTAs/SM.
#define XS_STRIDE 132
#define KV_WSB  (64*XS_STRIDE)                    // word offset of Wsb
#define KV_SMEM ((64*XS_STRIDE + 128*36)*4)
__global__ void __launch_bounds__(256, 2) kv_kernel(
    const float* __restrict__ rf, const float* __restrict__ unc,
    const float* __restrict__ ipb, const float* __restrict__ ipw)
{
    extern __shared__ float qsm[];
    float* Rs = qsm;                              // [64][132]
    uint32_t* Wsb = (uint32_t*)(qsm + KV_WSB);    // [128][36] bf16x2
    uint32_t smem = smem_to_u32(qsm);

    int tid = threadIdx.x, wid = tid >> 5, l = tid & 31;
    int t0  = blockIdx.x * 128;
    int win = blockIdx.x / 18;
    int nbase = (blockIdx.x % 18) * 128;
    int pixbase = (win >> 2)*WS*HW + (win & 3)*WS;

#pragma unroll
    for (int it = 0; it < 8; it++) {
        int gidx = it*256 + tid;
        int c = gidx >> 5, g = gidx & 31;
        int n = nbase + g*4;
        int pix = pixbase + (n/WS)*HW + (n%WS);
        CP16(smem + (c*XS_STRIDE + g*4)*4, rf + c*NPIX + pix);
    }
    CP_COMMIT();

    // Wsb built from direct gmem loads (L2-hot), under cp.async shadow
#pragma unroll
    for (int i = tid; i < 4096; i += 256) {
        int o = i >> 5, u = i & 31;
        float2 w = *(const float2*)(ipw + (64 + o)*64 + 2*u);
        CVT_BF16X2(Wsb[o*36 + u], w.x, w.y);
    }

    if (tid < 128) {
        int n = nbase + tid;
        int pix = pixbase + (n/WS)*HW + (n%WS);
        g_U[t0 + tid] = (unc[pix] > 0.01f) ? 0.f : -150.f;
    }

    CP_WAIT0();
    __syncthreads();

    int r = wid*16 + (l >> 2);
    uint32_t ar[4][4];
#pragma unroll
    for (int kk = 0; kk < 4; kk++) {
        int k0 = kk*16 + 2*(l & 3);
#pragma unroll
        for (int half = 0; half < 2; half++) {
            int k = k0 + half*8;
            CVT_BF16X2(ar[kk][2*half],   Rs[k*XS_STRIDE + r],     Rs[(k+1)*XS_STRIDE + r]);
            CVT_BF16X2(ar[kk][2*half+1], Rs[k*XS_STRIDE + r + 8], Rs[(k+1)*XS_STRIDE + r + 8]);
        }
    }

#pragma unroll
    for (int seg = 0; seg < 2; seg++) {
        float acc[8][4];
#pragma unroll
        for (int nb = 0; nb < 8; nb++)
#pragma unroll
            for (int c = 0; c < 4; c++) acc[nb][c] = 0.f;

#pragma unroll
        for (int nb = 0; nb < 8; nb++) {
            int o = seg*64 + nb*8 + (l >> 2);
#pragma unroll
            for (int kk = 0; kk < 4; kk++) {
                uint32_t b0 = Wsb[o*36 + kk*8 + (l & 3)];
                uint32_t b1 = Wsb[o*36 + kk*8 + (l & 3) + 4];
                MMA_BF16(acc[nb], ar[kk][0], ar[kk][1], ar[kk][2], ar[kk][3], b0, b1);
            }
        }

        __nv_bfloat16* dst = (seg == 0) ? g_Kb : g_Vb;
#pragma unroll
        for (int nb = 0; nb < 8; nb++) {
            int col = nb*8 + 2*(l & 3);
            float2 bv = *(const float2*)(ipb + 64 + seg*64 + col);
            uint32_t lo, hi;
            CVT_BF16X2(lo, acc[nb][0] + bv.x, acc[nb][1] + bv.y);
            CVT_BF16X2(hi, acc[nb][2] + bv.x, acc[nb][3] + bv.y);
            *(uint32_t*)(dst + (size_t)(t0 + r)*64 + col)     = lo;
            *(uint32_t*)(dst + (size_t)(t0 + r + 8)*64 + col) = hi;
        }
    }
}

// ---------------- kernel 2: attn with fused Q-projection + refine ---------
#define QOFF   0
#define KOFF   16384
#define VOFF   49152
#define UCOFF  81920
#define ATTN_SMEM (81920 + 1024)

__device__ __forceinline__ void issue_tile(uint32_t smem, int win, int ct, int buf, int tid)
{
    int c0 = ct * 128;
    const char* Kg = (const char*)g_Kb + ((size_t)(win*NTOK + c0))*128;
    const char* Vg = (const char*)g_Vb + ((size_t)(win*NTOK + c0))*128;
    uint32_t kb = smem + KOFF + buf*16384;
    uint32_t vb = smem + VOFF + buf*16384;
#pragma unroll
    for (int i = 0; i < 4; i++) {
        int li = i*256 + tid, r = li >> 3, q = li & 7;
        uint32_t off = r*128 + ((q*16) ^ ((r & 7) << 4));
        CP16(kb + off, Kg + r*128 + q*16);
        CP16(vb + off, Vg + r*128 + q*16);
    }
    if (tid < 128)
        CP4(smem + UCOFF + buf*512 + tid*4, (const char*)(g_U + win*NTOK + c0 + tid));
}

__global__ void __launch_bounds__(256, 2) attn_kernel(const float* __restrict__ x,
                                                      const float* __restrict__ ipb,
                                                      const float* __restrict__ ipw)
{
    extern __shared__ char smc[];
    uint32_t smem = smem_to_u32(smc);
    int tid = threadIdx.x, wid = tid >> 5, l = tid & 31;
    int win = blockIdx.y, r0 = blockIdx.x * 128;
    int pixbase = (win >> 2)*WS*HW + (win & 3)*WS;
    const float LC = 0.18033688011112042f;   // 0.125 * log2(e)

    // ---- prologue: x tile (fp32) into K region; Wq packed at QOFF via LDG
#pragma unroll
    for (int it = 0; it < 8; it++) {
        int gidx = it*256 + tid;
        int c = gidx >> 5, g = gidx & 31;
        int n = r0 + g*4;
        int pix = pixbase + (n/WS)*HW + (n%WS);
        CP16(smem + KOFF + (c*XS_STRIDE + g*4)*4, x + c*NPIX + pix);
    }
    CP_COMMIT();
    {
        uint32_t* Wsb = (uint32_t*)(smc + QOFF);
#pragma unroll
        for (int i = tid; i < 2048; i += 256) {
            int o = i >> 5, u = i & 31;
            float2 w = *(const float2*)(ipw + o*64 + 2*u);
            CVT_BF16X2(Wsb[o*36 + u], w.x, w.y);
        }
    }

    int row_a = wid*16 + (l >> 2);
    bool urow0 = g_U[win*NTOK + r0 + row_a]     > -1.f;
    bool urow1 = g_U[win*NTOK + r0 + row_a + 8] > -1.f;
    float LC0 = urow0 ? LC : 0.f;
    float LC1 = urow1 ? LC : 0.f;
    float M0 = urow0 ? 1.f : 0.f;
    float M1 = urow1 ? 1.f : 0.f;

    CP_WAIT0();
    __syncthreads();

    // build x A-fragments from fp32 smem
    uint32_t axf[4][4];
    {
        const float* Xs = (const float*)(smc + KOFF);
        int r = row_a;
#pragma unroll
        for (int kk = 0; kk < 4; kk++) {
            int k0 = kk*16 + 2*(l & 3);
#pragma unroll
            for (int half = 0; half < 2; half++) {
                int k = k0 + half*8;
                CVT_BF16X2(axf[kk][2*half],   Xs[k*XS_STRIDE + r],     Xs[(k+1)*XS_STRIDE + r]);
                CVT_BF16X2(axf[kk][2*half+1], Xs[k*XS_STRIDE + r + 8], Xs[(k+1)*XS_STRIDE + r + 8]);
            }
        }
    }
    __syncthreads();                              // x reads done; K region reusable

    issue_tile(smem, win, 0, 0, tid);
    CP_COMMIT();
    issue_tile(smem, win, 1, 1, tid);
    CP_COMMIT();

    // Q = x*Wq^T (+bq), accumulators repacked directly as S-GEMM A-fragments
    uint32_t qa[4][4];
    {
        const uint32_t* Wsb = (const uint32_t*)(smc + QOFF);
        float accQ[8][4];
#pragma unroll
        for (int nb = 0; nb < 8; nb++)
#pragma unroll
            for (int c = 0; c < 4; c++) accQ[nb][c] = 0.f;
#pragma unroll
        for (int nb = 0; nb < 8; nb++) {
            int o = nb*8 + (l >> 2);
#pragma unroll
            for (int kk = 0; kk < 4; kk++) {
                uint32_t b0 = Wsb[o*36 + kk*8 + (l & 3)];
                uint32_t b1 = Wsb[o*36 + kk*8 + (l & 3) + 4];
                MMA_BF16(accQ[nb], axf[kk][0], axf[kk][1], axf[kk][2], axf[kk][3], b0, b1);
            }
        }
#pragma unroll
        for (int kk = 0; kk < 4; kk++) {
            int c0 = kk*16 + 2*(l & 3);
            float2 bl = *(const float2*)(ipb + c0);
            float2 bh = *(const float2*)(ipb + c0 + 8);
            CVT_BF16X2(qa[kk][0], accQ[2*kk][0] + bl.x,   accQ[2*kk][1] + bl.y);
            CVT_BF16X2(qa[kk][1], accQ[2*kk][2] + bl.x,   accQ[2*kk][3] + bl.y);
            CVT_BF16X2(qa[kk][2], accQ[2*kk+1][0] + bh.x, accQ[2*kk+1][1] + bh.y);
            CVT_BF16X2(qa[kk][3], accQ[2*kk+1][2] + bh.x, accQ[2*kk+1][3] + bh.y);
        }
    }

    float o[8][4];
#pragma unroll
    for (int j = 0; j < 8; j++)
#pragma unroll
        for (int c = 0; c < 4; c++) o[j][c] = 0.f;
    float rsum0 = 0.f, rsum1 = 0.f;

    int m = l >> 3;
    uint32_t xr = (uint32_t)(l & 7) << 4;
    int nrow_b = (m >> 1)*8 + (l & 7);
    int krow_b = (m & 1)*8 + (l & 7);
    const float* ucsm = (const float*)(smc + UCOFF);

    CP_WAIT1();
    __syncthreads();

#pragma unroll 1
    for (int ct = 0; ct < 18; ct++) {
        uint32_t kb = smem + KOFF + (ct & 1)*16384;
        uint32_t vb = smem + VOFF + (ct & 1)*16384;

#pragma unroll
        for (int h = 0; h < 2; h++) {
            float s[8][4];
#pragma unroll
            for (int j = 0; j < 8; j++)
#pragma unroll
                for (int c = 0; c < 4; c++) s[j][c] = 0.f;

#pragma unroll
            for (int kk = 0; kk < 4; kk++) {
                uint32_t cb = ((uint32_t)(kk*32 + (m & 1)*16)) ^ xr;
#pragma unroll
                for (int jb = 0; jb < 4; jb++) {
                    uint32_t addr = kb + (16*(4*h + jb) + nrow_b)*128 + cb;
                    uint32_t b0, b1, b2, b3;
                    LDSM_X4(b0, b1, b2, b3, addr);
                    MMA_BF16(s[2*jb],   qa[kk][0], qa[kk][1], qa[kk][2], qa[kk][3], b0, b1);
                    MMA_BF16(s[2*jb+1], qa[kk][0], qa[kk][1], qa[kk][2], qa[kk][3], b2, b3);
                }
            }

            const float* ucb = ucsm + (ct & 1)*128 + h*64 + 2*(l & 3);
            uint32_t pc01[8], pc23[8];
#pragma unroll
            for (int j = 0; j < 8; j++) {
                float2 cm = *(const float2*)(ucb + 8*j);
                float p0, p1, p2, p3;
                EX2F(p0, fmaf(s[j][0], LC0, cm.x*M0));
                EX2F(p1, fmaf(s[j][1], LC0, cm.y*M0));
                EX2F(p2, fmaf(s[j][2], LC1, cm.x*M1));
                EX2F(p3, fmaf(s[j][3], LC1, cm.y*M1));
                rsum0 += p0 + p1;
                rsum1 += p2 + p3;
                CVT_BF16X2(pc01[j], p0, p1);
                CVT_BF16X2(pc23[j], p2, p3);
            }

#pragma unroll
            for (int kc = 0; kc < 4; kc++) {
                uint32_t ra = vb + (16*(4*h + kc) + krow_b)*128;
#pragma unroll
                for (int jb = 0; jb < 4; jb++) {
                    uint32_t addr = ra + (((uint32_t)(jb*32 + (m >> 1)*16)) ^ xr);
                    uint32_t v0, v1, v2, v3;
                    LDSM_X4T(v0, v1, v2, v3, addr);
                    MMA_BF16(o[2*jb],   pc01[2*kc], pc23[2*kc], pc01[2*kc+1], pc23[2*kc+1], v0, v1);
                    MMA_BF16(o[2*jb+1], pc01[2*kc], pc23[2*kc], pc01[2*kc+1], pc23[2*kc+1], v2, v3);
                }
            }
        }

        __syncthreads();
        if (ct + 2 < 18) { issue_tile(smem, win, ct + 2, ct & 1, tid); CP_COMMIT(); }
        if (ct + 1 < 18) {
            if (ct + 2 < 18) { CP_WAIT1(); } else { CP_WAIT0(); }
            __syncthreads();
        }
    }

    rsum0 += __shfl_xor_sync(0xffffffffu, rsum0, 1);
    rsum0 += __shfl_xor_sync(0xffffffffu, rsum0, 2);
    rsum1 += __shfl_xor_sync(0xffffffffu, rsum1, 1);
    rsum1 += __shfl_xor_sync(0xffffffffu, rsum1, 2);
    float inv0 = 1.f / rsum0, inv1 = 1.f / rsum1;

    // fused refine: refined = x + (O/rsum)*M^T + b2, written fp16 NHWC
    __syncthreads();
    {
        const char* Mg = (const char*)g_Mb;
#pragma unroll
        for (int i = 0; i < 2; i++) {
            int li = i*256 + tid, r = li >> 3, q = li & 7;
            CP16(smem + QOFF + r*128 + ((q*16) ^ ((r & 7) << 4)), Mg + r*128 + q*16);
        }
        CP_COMMIT(); CP_WAIT0();
    }
    __syncthreads();

    uint32_t af[4][4];
#pragma unroll
    for (int kk = 0; kk < 4; kk++) {
        CVT_BF16X2(af[kk][0], o[2*kk][0]*inv0,   o[2*kk][1]*inv0);
        CVT_BF16X2(af[kk][1], o[2*kk][2]*inv1,   o[2*kk][3]*inv1);
        CVT_BF16X2(af[kk][2], o[2*kk+1][0]*inv0, o[2*kk+1][1]*inv0);
        CVT_BF16X2(af[kk][3], o[2*kk+1][2]*inv1, o[2*kk+1][3]*inv1);
    }

    float dd[8][4];
#pragma unroll
    for (int j = 0; j < 8; j++)
#pragma unroll
        for (int c = 0; c < 4; c++) dd[j][c] = 0.f;

#pragma unroll
    for (int kk = 0; kk < 4; kk++) {
        uint32_t cb = ((uint32_t)(kk*32 + (m & 1)*16)) ^ xr;
#pragma unroll
        for (int jb = 0; jb < 4; jb++) {
            uint32_t addr = smem + QOFF + (16*jb + nrow_b)*128 + cb;
            uint32_t b0, b1, b2, b3;
            LDSM_X4(b0, b1, b2, b3, addr);
            MMA_BF16(dd[2*jb],   af[kk][0], af[kk][1], af[kk][2], af[kk][3], b0, b1);
            MMA_BF16(dd[2*jb+1], af[kk][0], af[kk][1], af[kk][2], af[kk][3], b2, b3);
        }
    }

    int n0 = r0 + row_a;
    int n1 = n0 + 8;
    int px0 = pixbase + (n0/WS)*HW + n0%WS;
    int px1 = pixbase + (n1/WS)*HW + n1%WS;
#pragma unroll
    for (int jb = 0; jb < 4; jb++) {
#pragma unroll
        for (int hh = 0; hh < 2; hh++) {
            int c = 16*jb + 8*hh + 2*(l & 3);
            int j = 2*jb + hh;
            float2 b2v = *(const float2*)(g_b2 + c);
            *(uint32_t*)(g_refh + (size_t)px0*64 + c) =
                pack_h2(x[(size_t)c*NPIX + px0]     + dd[j][0] + b2v.x,
                        x[(size_t)(c+1)*NPIX + px0] + dd[j][1] + b2v.y);
            *(uint32_t*)(g_refh + (size_t)px1*64 + c) =
                pack_h2(x[(size_t)c*NPIX + px1]     + dd[j][2] + b2v.x,
                        x[(size_t)(c+1)*NPIX + px1] + dd[j][3] + b2v.y);
        }
    }
}

// ---------------- kernel 3: conv3x3 fp16 MMA via ldmatrix (R13 proven) ----
#define CONVW_OFF 0
#define CONVI_OFF 73728
#define CONV_SMEM (73728 + 43520 + 256)

__global__ void __launch_bounds__(256) conv_kernel(
    const float* __restrict__ b3, const float* __restrict__ w4,
    const float* __restrict__ b4v, float* __restrict__ out)
{
    extern __shared__ char csm[];
    uint32_t smem = smem_to_u32(csm);

    int tid = threadIdx.x, wid = tid >> 5, l = tid & 31;
    int cx0 = blockIdx.x*32, y0 = blockIdx.y*8;

    for (int i = tid; i < 4608; i += 256) {
        int row = i >> 3, q = i & 7;
        CP16(smem + CONVW_OFF + row*128 + ((q*16) ^ ((row & 7) << 4)),
             g_W3h + row*64 + q*8);
    }
    for (int i = tid; i < 2720; i += 256) {
        int p = i >> 3, q = i & 7;
        int ry = p / 34, rcx = p - ry*34;
        int gy = y0 - 1 + ry, gx = cx0 - 1 + rcx;
        bool ok = ((unsigned)gy < HW) && ((unsigned)gx < HW);
        const __half* src = g_refh + ((size_t)(ok ? (gy*HW + gx) : 0))*64 + q*8;
        CP16Z(smem + CONVI_OFF + p*128 + ((q*16) ^ ((p & 7) << 4)),
              src, ok ? 16u : 0u);
    }
    CP_COMMIT();
    CP_WAIT0();
    __syncthreads();

    float acc[2][8][4];
#pragma unroll
    for (int mb = 0; mb < 2; mb++)
#pragma unroll
        for (int nb = 0; nb < 8; nb++)
#pragma unroll
            for (int c = 0; c < 4; c++) acc[mb][nb][c] = 0.f;

    int m = l >> 3;
    int wr = wid;

#pragma unroll 1
    for (int tap = 0; tap < 9; tap++) {
        int dyv = tap / 3, dxv = tap % 3;
        int arow_base = (wr + dyv)*34 + dxv + (m & 1)*8 + (l & 7);
#pragma unroll
        for (int kk = 0; kk < 4; kk++) {
            uint32_t bf[8][2];
#pragma unroll
            for (int jb = 0; jb < 4; jb++) {
                uint32_t addr = smem + CONVW_OFF
                    + (tap*64 + 16*jb + (m >> 1)*8 + (l & 7))*128
                    + (((uint32_t)(kk*32 + (m & 1)*16)) ^ ((uint32_t)(l & 7) << 4));
                LDSM_X4(bf[2*jb][0], bf[2*jb][1], bf[2*jb+1][0], bf[2*jb+1][1], addr);
            }
#pragma unroll
            for (int mb = 0; mb < 2; mb++) {
                int arow = arow_base + 16*mb;
                uint32_t addr = smem + CONVI_OFF + arow*128 +
                    (((uint32_t)(kk*32 + (m >> 1)*16)) ^ (((uint32_t)(arow & 7)) << 4));
                uint32_t a0, a1, a2, a3;
                LDSM_X4(a0, a1, a2, a3, addr);
#pragma unroll
                for (int nb = 0; nb < 8; nb++)
                    MMA_F16(acc[mb][nb], a0, a1, a2, a3, bf[nb][0], bf[nb][1]);
            }
        }
    }

    int y = y0 + wr;
    float b4 = b4v[0];
    float s[2][2] = {{0.f, 0.f}, {0.f, 0.f}};
#pragma unroll
    for (int mb = 0; mb < 2; mb++) {
        int x1 = cx0 + 16*mb + (l >> 2);
        int x2 = x1 + 8;
#pragma unroll
        for (int nb = 0; nb < 8; nb++) {
            int oc = 8*nb + 2*(l & 3);
            float bv0 = __ldg(b3 + oc), bv1 = __ldg(b3 + oc + 1);
            float w40 = __ldg(w4 + oc), w41 = __ldg(w4 + oc + 1);
            float r00 = fmaxf(acc[mb][nb][0] + bv0, 0.f);
            float r01 = fmaxf(acc[mb][nb][1] + bv1, 0.f);
            float r10 = fmaxf(acc[mb][nb][2] + bv0, 0.f);
            float r11 = fmaxf(acc[mb][nb][3] + bv1, 0.f);
            out[(size_t)oc*NPIX     + y*HW + x1] = r00;
            out[(size_t)(oc+1)*NPIX + y*HW + x1] = r01;
            out[(size_t)oc*NPIX     + y*HW + x2] = r10;
            out[(size_t)(oc+1)*NPIX + y*HW + x2] = r11;
            s[mb][0] += r00*w40 + r01*w41;
            s[mb][1] += r10*w40 + r11*w41;
        }
    }
#pragma unroll
    for (int mb = 0; mb < 2; mb++) {
#pragma unroll
        for (int h = 0; h < 2; h++) {
            s[mb][h] += __shfl_xor_sync(0xffffffffu, s[mb][h], 1);
            s[mb][h] += __shfl_xor_sync(0xffffffffu, s[mb][h], 2);
        }
    }
    if ((l & 3) == 0) {
#pragma unroll
        for (int mb = 0; mb < 2; mb++) {
            int x1 = cx0 + 16*mb + (l >> 2);
            out[(size_t)64*NPIX + y*HW + x1]     = s[mb][0] + b4;
            out[(size_t)64*NPIX + y*HW + x1 + 8] = s[mb][1] + b4;
        }
    }
    {
        int yy = y0 + (tid >> 5), xx = cx0 + (tid & 31);
        int ry = yy % WS, rx = xx % WS;
        float pm = ((ry == 0) | (ry == WS-1) | (rx == 0) | (rx == WS-1)) ? 0.6f : 1.0f;
        out[(size_t)65*NPIX + yy*HW + xx] = pm;
    }
}

// ---------------- launch ---------------------------------------------------
extern "C" void kernel_launch(void* const* d_in, const int* in_sizes, int n_in,
                              void* d_out, int out_size)
{
    const float* x    = (const float*)d_in[0];
    const float* rf   = (const float*)d_in[1];
    const float* unc  = (const float*)d_in[2];
    const float* ipw  = (const float*)d_in[3];
    const float* ipb  = (const float*)d_in[4];
    const float* wout = (const float*)d_in[5];
    const float* bout = (const float*)d_in[6];
    const float* w1   = (const float*)d_in[7];
    const float* b1   = (const float*)d_in[8];
    const float* w3   = (const float*)d_in[9];
    const float* b3   = (const float*)d_in[10];
    const float* w4   = (const float*)d_in[11];
    const float* b4   = (const float*)d_in[12];
    float* out = (float*)d_out;

    static bool attr_set = false;
    if (!attr_set) {
        cudaFuncSetAttribute(attn_kernel, cudaFuncAttributeMaxDynamicSharedMemorySize, ATTN_SMEM);
        cudaFuncSetAttribute(conv_kernel, cudaFuncAttributeMaxDynamicSharedMemorySize, CONV_SMEM);
        cudaFuncSetAttribute(kv_kernel, cudaFuncAttributeMaxDynamicSharedMemorySize, KV_SMEM);
        attr_set = true;
    }

    prep_kernel<<<64, 64>>>(w1, b1, wout, bout, w3);
    kv_kernel<<<288, 256, KV_SMEM>>>(rf, unc, ipb, ipw);
    dim3 ag(18, 16);
    attn_kernel<<<ag, 256, ATTN_SMEM>>>(x, ipb, ipw);
    dim3 cg(6, 24);
    conv_kernel<<<cg, 256, CONV_SMEM>>>(b3, w4, b4, out);
}